// round 6
// baseline (speedup 1.0000x reference)
#include <cuda_runtime.h>
#include <cuda_bf16.h>
#include <cstdint>

#define B_   128
#define S_   512
#define E_   300
#define KP   320     // padded K for GEMM
#define H_   128
#define G4   512     // 4*H
#define T_   12
#define SOS_ 3
#define EOS_ 4
#define NEGV (-10000.0f)

// ---------------- scratch (static device allocations) ----------------
__device__ __align__(16) __nv_bfloat16 g_emb[(size_t)B_*S_*KP];   // [65536][320]
__device__ __align__(16) __nv_bfloat16 g_wcat[1024*KP];           // [1024][320]
__device__ __align__(16) __nv_bfloat16 g_whh[2*G4*H_];            // [2][512][128]
__device__ float g_bias[1024];
__device__ float g_pre[(size_t)2*B_*S_*G4];                       // [2][128][512][512] fp32
__device__ __align__(16) __nv_bfloat16 g_hcat[(size_t)B_*S_*2*H_]; // [65536][256] bf16
__device__ float g_y[(size_t)B_*S_*T_];                           // [65536][12]

// ---------------- helpers ----------------
__device__ __forceinline__ float tanhapx(float x) {
    float r; asm("tanh.approx.f32 %0, %1;" : "=f"(r) : "f"(x)); return r;
}
__device__ __forceinline__ float sigf(float x) {
    return 0.5f + 0.5f * tanhapx(0.5f * x);
}
__device__ __forceinline__ void cp16(void* smem, const void* gmem) {
    uint32_t s = (uint32_t)__cvta_generic_to_shared(smem);
    asm volatile("cp.async.cg.shared.global [%0], [%1], 16;\n" :: "r"(s), "l"(gmem) : "memory");
}
__device__ __forceinline__ void cp_commit() {
    asm volatile("cp.async.commit_group;\n" ::: "memory");
}
template<int N> __device__ __forceinline__ void cp_wait() {
    asm volatile("cp.async.wait_group %0;\n" :: "n"(N) : "memory");
}

// ---------------- K1: embedding gather -> bf16, K-padded (vectorized) ----------------
__global__ void k_prep_emb(const int* __restrict__ x, const float* __restrict__ embed) {
    const int row = blockIdx.x;          // 0..65535
    const int p   = threadIdx.x;         // 0..159 (pair index)
    const int xv  = x[row];
    __nv_bfloat162 v;
    if (p < E_ / 2) {
        float2 f = *(const float2*)&embed[(size_t)xv * E_ + p * 2];
        v = __floats2bfloat162_rn(f.x, f.y);
    } else {
        v = __floats2bfloat162_rn(0.0f, 0.0f);
    }
    *(__nv_bfloat162*)&g_emb[(size_t)row * KP + p * 2] = v;
}

// ---------------- K1b: weight packing ----------------
__global__ void k_prep_w(const float* __restrict__ Wih_f, const float* __restrict__ Whh_f,
                         const float* __restrict__ b_f,
                         const float* __restrict__ Wih_b, const float* __restrict__ Whh_b,
                         const float* __restrict__ b_b) {
    int idx = blockIdx.x * blockDim.x + threadIdx.x;
    const int NW = 1024 * KP;
    const int NH = 2 * G4 * H_;
    if (idx < NW) {
        int r = idx / KP, k = idx % KP;
        float v = 0.0f;
        if (k < E_) v = (r < G4) ? Wih_f[r * E_ + k] : Wih_b[(r - G4) * E_ + k];
        g_wcat[idx] = __float2bfloat16(v);
    } else if (idx < NW + NH) {
        int i = idx - NW;
        int d = i / (G4 * H_);
        int rem = i % (G4 * H_);
        float v = d ? Whh_b[rem] : Whh_f[rem];
        g_whh[i] = __float2bfloat16(v);
    } else if (idx < NW + NH + 1024) {
        int n = idx - NW - NH;
        g_bias[n] = (n < G4) ? b_f[n] : b_b[n - G4];
    }
}

// ---------------- K2: input GEMM (bf16 mma.sync, fp32 accum, cp.async 3-stage) ----------------
#define BM 128
#define BN 64
#define BK 32
#define SA 40
#define KITERS (KP / BK)   // 10
#define NSTG 3

__global__ __launch_bounds__(256) void k_gemm_in() {
    __shared__ __align__(16) __nv_bfloat16 As[NSTG][BM * SA];
    __shared__ __align__(16) __nv_bfloat16 Bs[NSTG][BN * SA];
    const int m0 = blockIdx.y * BM;
    const int n0 = blockIdx.x * BN;
    const int tid = threadIdx.x;
    const int warp = tid >> 5, lane = tid & 31;
    const int wm = warp >> 1, wn = warp & 1;

    float acc[2][4][4];
    #pragma unroll
    for (int a = 0; a < 2; a++)
        #pragma unroll
        for (int b = 0; b < 4; b++)
            #pragma unroll
            for (int c = 0; c < 4; c++) acc[a][b][c] = 0.0f;

    const int lr = lane >> 2, lc = (lane & 3) * 2;
    const int ldr = tid >> 2, seg = tid & 3;

    #pragma unroll
    for (int p = 0; p < 2; p++) {
        const int kt = p * BK;
        cp16(&As[p][ldr * SA + seg * 8],        &g_emb[(size_t)(m0 + ldr) * KP + kt + seg * 8]);
        cp16(&As[p][(ldr + 64) * SA + seg * 8], &g_emb[(size_t)(m0 + ldr + 64) * KP + kt + seg * 8]);
        cp16(&Bs[p][ldr * SA + seg * 8],        &g_wcat[(size_t)(n0 + ldr) * KP + kt + seg * 8]);
        cp_commit();
    }

    for (int it = 0; it < KITERS; it++) {
        if (it + 2 < KITERS) {
            const int kt = (it + 2) * BK;
            const int st = (it + 2) % NSTG;
            cp16(&As[st][ldr * SA + seg * 8],        &g_emb[(size_t)(m0 + ldr) * KP + kt + seg * 8]);
            cp16(&As[st][(ldr + 64) * SA + seg * 8], &g_emb[(size_t)(m0 + ldr + 64) * KP + kt + seg * 8]);
            cp16(&Bs[st][ldr * SA + seg * 8],        &g_wcat[(size_t)(n0 + ldr) * KP + kt + seg * 8]);
            cp_commit();
            cp_wait<2>();
        } else if (it + 1 < KITERS) {
            cp_wait<1>();
        } else {
            cp_wait<0>();
        }
        __syncthreads();
        const int st = it % NSTG;
        #pragma unroll
        for (int ks = 0; ks < 2; ks++) {
            const int kb = ks * 16;
            uint32_t bfr[4][2];
            #pragma unroll
            for (int ni = 0; ni < 4; ni++) {
                int nrow = wn * 32 + ni * 8 + lr;
                bfr[ni][0] = *(const uint32_t*)&Bs[st][nrow * SA + kb + lc];
                bfr[ni][1] = *(const uint32_t*)&Bs[st][nrow * SA + kb + lc + 8];
            }
            #pragma unroll
            for (int mi = 0; mi < 2; mi++) {
                int mrow = wm * 32 + mi * 16;
                uint32_t a0 = *(const uint32_t*)&As[st][(mrow + lr    ) * SA + kb + lc];
                uint32_t a1 = *(const uint32_t*)&As[st][(mrow + lr + 8) * SA + kb + lc];
                uint32_t a2 = *(const uint32_t*)&As[st][(mrow + lr    ) * SA + kb + lc + 8];
                uint32_t a3 = *(const uint32_t*)&As[st][(mrow + lr + 8) * SA + kb + lc + 8];
                #pragma unroll
                for (int ni = 0; ni < 4; ni++) {
                    asm volatile(
                        "mma.sync.aligned.m16n8k16.row.col.f32.bf16.bf16.f32 "
                        "{%0,%1,%2,%3}, {%4,%5,%6,%7}, {%8,%9}, {%0,%1,%2,%3};\n"
                        : "+f"(acc[mi][ni][0]), "+f"(acc[mi][ni][1]),
                          "+f"(acc[mi][ni][2]), "+f"(acc[mi][ni][3])
                        : "r"(a0), "r"(a1), "r"(a2), "r"(a3),
                          "r"(bfr[ni][0]), "r"(bfr[ni][1]));
                }
            }
        }
        __syncthreads();
    }
    // epilogue: add bias, scatter fp32 to PRE[d][b][s][j]
    #pragma unroll
    for (int mi = 0; mi < 2; mi++) {
        #pragma unroll
        for (int ni = 0; ni < 4; ni++) {
            int m = m0 + wm * 32 + mi * 16 + lr;
            int n = n0 + wn * 32 + ni * 8 + lc;
            int d = n >> 9, j = n & 511;
            float bias0 = g_bias[n], bias1 = g_bias[n + 1];
            {
                int bb = m >> 9, ss = m & 511;
                size_t base = (((size_t)(d * B_ + bb) * S_ + ss) * G4 + j);
                *(float2*)&g_pre[base] = make_float2(acc[mi][ni][0] + bias0,
                                                     acc[mi][ni][1] + bias1);
            }
            {
                int m2 = m + 8;
                int bb = m2 >> 9, ss = m2 & 511;
                size_t base = (((size_t)(d * B_ + bb) * S_ + ss) * G4 + j);
                *(float2*)&g_pre[base] = make_float2(acc[mi][ni][2] + bias0,
                                                     acc[mi][ni][3] + bias1);
            }
        }
    }
}

// ---------------- K3: tensor-core recurrence, 2-CTA cluster split ----------------
// 64 blocks = 32 clusters of 2. Cluster = (dir, 8-batch group); CTA q handles
// gate columns for cells [q*64, q*64+64) -> N=256 per CTA, 8 warps, 256 thr.
// Each CTA computes h for its 64 cells, writes it into BOTH CTAs' h_sm via
// st.shared::cluster; two mbarriers (one per h buffer) with count=2 gate steps.
#define HS 136   // h_sm row stride in bf16 (272B -> conflict-free ldmatrix)

__global__ __launch_bounds__(256, 1) __cluster_dims__(2, 1, 1) void k_lstm() {
    __shared__ __align__(16) __nv_bfloat16 h_sm[2][16][HS];
    __shared__ __align__(8) uint64_t mbar[2];

    const int cid = blockIdx.x >> 1;       // cluster id
    const int q   = blockIdx.x & 1;        // rank within cluster
    const int d   = cid >> 4;
    const int bg  = cid & 15;
    const int b0  = bg * 8;
    const int tid = threadIdx.x;
    const int w = tid >> 5, l = tid & 31;
    const int r = l >> 2, cpair = (l & 3) * 2;

    const uint32_t smem_h = (uint32_t)__cvta_generic_to_shared(&h_sm[0][0][0]);
    const uint32_t smem_bar = (uint32_t)__cvta_generic_to_shared(&mbar[0]);

    // preload B fragments (Whh rows ni*128 + q*64 + w*8 + r): 64 regs
    uint32_t Bf[4][8][2];
    #pragma unroll
    for (int ni = 0; ni < 4; ni++) {
        const int n = ni * 128 + q * 64 + w * 8 + r;
        const __nv_bfloat16* src = &g_whh[((size_t)d * G4 + n) * H_ + cpair];
        #pragma unroll
        for (int tk = 0; tk < 8; tk++) {
            Bf[ni][tk][0] = *(const uint32_t*)&src[tk * 16];
            Bf[ni][tk][1] = *(const uint32_t*)&src[tk * 16 + 8];
        }
    }
    // zero both h buffers (rows 8-15 stay zero = M padding)
    for (int i = tid; i < 2 * 16 * HS; i += 256)
        ((__nv_bfloat16*)h_sm)[i] = __float2bfloat16(0.0f);

    if (tid == 0) {
        asm volatile("mbarrier.init.shared.b64 [%0], 2;\n" :: "r"(smem_bar) : "memory");
        asm volatile("mbarrier.init.shared.b64 [%0], 2;\n" :: "r"(smem_bar + 8) : "memory");
    }
    __syncthreads();
    asm volatile("barrier.cluster.arrive.aligned;\n" ::: "memory");
    asm volatile("barrier.cluster.wait.aligned;\n" ::: "memory");

    const int b     = b0 + r;
    const int cglob = q * 64 + w * 8 + cpair;        // cell index 0..127
    const int sgn   = d ? -1 : 1;
    const int se0   = d ? (S_ - 1) : 0;

    const float* preb = &g_pre[((size_t)(d * B_ + b) * S_ + se0) * G4 + cglob];
    __nv_bfloat16* hout = &g_hcat[((size_t)b * S_ + se0) * 256 + d * H_ + cglob];
    const int preb_step = sgn * G4;
    const int hout_step = sgn * 256;

    float2 pf[4];
    #pragma unroll
    for (int ni = 0; ni < 4; ni++)
        pf[ni] = *(const float2*)&preb[ni * 128];

    float cA = 0.0f, cB = 0.0f;
    const uint32_t abase0 = smem_h +
        ((l & 15) * HS + (l >> 4) * 8) * 2;
    // local & peer store addresses for h (row r, col cglob)
    const uint32_t hst_local = smem_h + (r * HS + cglob) * 2;   // buffer 0 base
    uint32_t hst_peer;
    asm volatile("mapa.shared::cluster.u32 %0, %1, %2;\n"
                 : "=r"(hst_peer) : "r"(hst_local), "r"(q ^ 1));
    uint32_t bar_peer;
    asm volatile("mapa.shared::cluster.u32 %0, %1, %2;\n"
                 : "=r"(bar_peer) : "r"(smem_bar), "r"(q ^ 1));

    int buf = 0;
    int phase[2] = {0, 0};
    #pragma unroll 1
    for (int s = 0; s < S_; s++) {
        // acc init = current pre-activations (bias folded in)
        float acc[4][4];
        #pragma unroll
        for (int ni = 0; ni < 4; ni++) {
            acc[ni][0] = pf[ni].x; acc[ni][1] = pf[ni].y;
            acc[ni][2] = 0.0f;     acc[ni][3] = 0.0f;
        }
        if (s < S_ - 1) preb += preb_step;
        #pragma unroll
        for (int ni = 0; ni < 4; ni++)
            pf[ni] = *(const float2*)&preb[ni * 128];

        const uint32_t abase = abase0 + (uint32_t)buf * (16 * HS * 2);
        #pragma unroll
        for (int tk = 0; tk < 8; tk++) {
            uint32_t a0, a1, a2, a3;
            asm volatile("ldmatrix.sync.aligned.m8n8.x4.shared.b16 {%0,%1,%2,%3}, [%4];\n"
                         : "=r"(a0), "=r"(a1), "=r"(a2), "=r"(a3)
                         : "r"(abase + tk * 32));
            #pragma unroll
            for (int ni = 0; ni < 4; ni++) {
                asm volatile(
                    "mma.sync.aligned.m16n8k16.row.col.f32.bf16.bf16.f32 "
                    "{%0,%1,%2,%3}, {%4,%5,%6,%7}, {%8,%9}, {%0,%1,%2,%3};\n"
                    : "+f"(acc[ni][0]), "+f"(acc[ni][1]),
                      "+f"(acc[ni][2]), "+f"(acc[ni][3])
                    : "r"(a0), "r"(a1), "r"(a2), "r"(a3),
                      "r"(Bf[ni][tk][0]), "r"(Bf[ni][tk][1]));
            }
        }

        // gates: ni 0=i, 1=f, 2=g, 3=o ; 2 cells (cglob, cglob+1), batch b
        cA = sigf(acc[1][0]) * cA + sigf(acc[0][0]) * tanhapx(acc[2][0]);
        cB = sigf(acc[1][1]) * cB + sigf(acc[0][1]) * tanhapx(acc[2][1]);
        float hA = sigf(acc[3][0]) * tanhapx(cA);
        float hB = sigf(acc[3][1]) * tanhapx(cB);

        __nv_bfloat162 hpk = __floats2bfloat162_rn(hA, hB);
        const int nb = buf ^ 1;
        const uint32_t boff = (uint32_t)nb * (16 * HS * 2);
        // local + peer h store
        asm volatile("st.shared.b32 [%0], %1;\n"
                     :: "r"(hst_local + boff), "r"(*(uint32_t*)&hpk) : "memory");
        asm volatile("st.shared::cluster.b32 [%0], %1;\n"
                     :: "r"(hst_peer + boff), "r"(*(uint32_t*)&hpk) : "memory");
        *(__nv_bfloat162*)hout = hpk;
        hout += hout_step;

        __syncthreads();
        if (tid == 0) {
            asm volatile("mbarrier.arrive.release.cluster.shared::cluster.b64 _, [%0];\n"
                         :: "r"(smem_bar + nb * 8) : "memory");
            asm volatile("mbarrier.arrive.release.cluster.shared::cluster.b64 _, [%0];\n"
                         :: "r"(bar_peer + nb * 8) : "memory");
        }
        // wait for both halves of h[nb]
        {
            const uint32_t ba = smem_bar + nb * 8;
            const uint32_t ph = (uint32_t)phase[nb];
            uint32_t done;
            asm volatile(
                "{\n\t.reg .pred p;\n\t"
                "mbarrier.try_wait.parity.acquire.cluster.shared::cta.b64 p, [%1], %2;\n\t"
                "selp.b32 %0, 1, 0, p;\n\t}"
                : "=r"(done) : "r"(ba), "r"(ph) : "memory");
            if (!done) {
                asm volatile(
                    "{\n\t.reg .pred P1;\n\t"
                    "WL_%=:\n\t"
                    "mbarrier.try_wait.parity.acquire.cluster.shared::cta.b64 P1, [%0], %1;\n\t"
                    "@P1 bra.uni WD_%=;\n\t"
                    "bra.uni WL_%=;\n\t"
                    "WD_%=:\n\t}"
                    :: "r"(ba), "r"(ph) : "memory");
            }
            phase[nb] ^= 1;
        }
        buf ^= 1;
    }
    asm volatile("barrier.cluster.arrive.aligned;\n" ::: "memory");
    asm volatile("barrier.cluster.wait.aligned;\n" ::: "memory");
}

// ---------------- K4: output linear (bf16 hcat) ----------------
__global__ void k_out(const float* __restrict__ Wout, const float* __restrict__ bout) {
    const int lr = threadIdx.x >> 4;
    const int t  = threadIdx.x & 15;
    const int row = blockIdx.x * 16 + lr;
    if (t >= T_) return;
    float acc = bout[t];
    const __nv_bfloat162* hv = (const __nv_bfloat162*)&g_hcat[(size_t)row * 256];
    const float2* wv = (const float2*)&Wout[t * 256];
    #pragma unroll 16
    for (int q = 0; q < 128; q++) {
        float2 h2 = __bfloat1622float2(hv[q]);
        float2 w2 = wv[q];
        acc += h2.x * w2.x + h2.y * w2.y;
    }
    g_y[(size_t)row * T_ + t] = acc;
}

// ---------------- K5: CRF forward + gold ----------------
__global__ void k_crf(const int* __restrict__ y0, const float* __restrict__ trans,
                      float* __restrict__ out) {
    __shared__ float tsm[T_ * T_];
    const int b = blockIdx.x;
    const int lane = threadIdx.x;
    for (int i = lane; i < T_ * T_; i += 32) tsm[i] = trans[i];
    __syncwarp();

    float trow[T_];
    const int irow = (lane < T_) ? lane : 0;
    #pragma unroll
    for (int jj = 0; jj < T_; jj++) trow[jj] = tsm[irow * T_ + jj];

    float score = (lane == SOS_) ? 0.0f : NEGV;
    const float* gyb = &g_y[(size_t)b * S_ * T_];

    float yv_next = (lane < T_) ? gyb[lane] : 0.0f;
    for (int s = 0; s < S_; s++) {
        float yv = yv_next;
        if (s + 1 < S_)
            yv_next = (lane < T_) ? gyb[(s + 1) * T_ + lane] : 0.0f;
        float v[T_];
        float mx = -1e30f;
        #pragma unroll
        for (int jj = 0; jj < T_; jj++) {
            float sj = __shfl_sync(0xffffffffu, score, jj);
            v[jj] = sj + trow[jj];
            mx = fmaxf(mx, v[jj]);
        }
        float sum = 0.0f;
        #pragma unroll
        for (int jj = 0; jj < T_; jj++) sum += __expf(v[jj] - mx);
        score = mx + __logf(sum) + yv;
    }
    float vz = (lane < T_) ? score + tsm[EOS_ * T_ + lane] : -1e30f;
    float mz = vz;
    #pragma unroll
    for (int o = 16; o; o >>= 1) mz = fmaxf(mz, __shfl_xor_sync(0xffffffffu, mz, o));
    float ez = (lane < T_) ? __expf(vz - mz) : 0.0f;
    #pragma unroll
    for (int o = 16; o; o >>= 1) ez += __shfl_xor_sync(0xffffffffu, ez, o);
    float Z = mz + __logf(ez);

    const int* yb = &y0[b * S_];
    float g = 0.0f;
    for (int s = lane; s < S_; s += 32) {
        int cur = yb[s];
        int prev = s ? yb[s - 1] : SOS_;
        g += gyb[s * T_ + cur] + tsm[cur * T_ + prev];
    }
    #pragma unroll
    for (int o = 16; o; o >>= 1) g += __shfl_xor_sync(0xffffffffu, g, o);
    if (lane == 0) {
        g += tsm[EOS_ * T_ + yb[S_ - 1]];
        out[b] = Z - g;
    }
}

// ---------------- launcher ----------------
extern "C" void kernel_launch(void* const* d_in, const int* in_sizes, int n_in,
                              void* d_out, int out_size) {
    const int*   x     = (const int*)d_in[0];
    const int*   y0    = (const int*)d_in[1];
    const float* embed = (const float*)d_in[2];
    const float* Wih_f = (const float*)d_in[3];
    const float* Whh_f = (const float*)d_in[4];
    const float* b_f   = (const float*)d_in[5];
    const float* Wih_b = (const float*)d_in[6];
    const float* Whh_b = (const float*)d_in[7];
    const float* b_b   = (const float*)d_in[8];
    const float* Wout  = (const float*)d_in[9];
    const float* bout  = (const float*)d_in[10];
    const float* trans = (const float*)d_in[11];
    float* out = (float*)d_out;

    k_prep_emb<<<B_ * S_, KP / 2>>>(x, embed);

    const int prep_total = 1024 * KP + 2 * G4 * H_ + 1024;
    k_prep_w<<<(prep_total + 255) / 256, 256>>>(Wih_f, Whh_f, b_f, Wih_b, Whh_b, b_b);

    dim3 gg(1024 / BN, (B_ * S_) / BM);
    k_gemm_in<<<gg, 256>>>();

    k_lstm<<<64, 256>>>();

    k_out<<<(B_ * S_) / 16, 256>>>(Wout, bout);

    k_crf<<<B_, 32>>>(y0, trans, out);
}

// round 8
// speedup vs baseline: 1.1609x; 1.1609x over previous
#include <cuda_runtime.h>
#include <cuda_bf16.h>
#include <cstdint>

#define B_   128
#define S_   512
#define E_   300
#define KP   320     // padded K for GEMM
#define H_   128
#define G4   512     // 4*H
#define T_   12
#define SOS_ 3
#define EOS_ 4
#define NEGV (-10000.0f)

// ---------------- scratch (static device allocations) ----------------
__device__ __align__(16) __nv_bfloat16 g_emb[(size_t)B_*S_*KP];   // [65536][320]
__device__ __align__(16) __nv_bfloat16 g_wcat[1024*KP];           // [1024][320]
__device__ __align__(16) __nv_bfloat16 g_whh[2*G4*H_];            // [2][512][128]
__device__ float g_bias[1024];
__device__ float g_pre[(size_t)2*B_*S_*G4];                       // [2][128][512][512] fp32
__device__ __align__(16) __nv_bfloat16 g_hcat[(size_t)B_*S_*2*H_]; // [65536][256] bf16
__device__ float g_y[(size_t)B_*S_*T_];                           // [65536][12]

// ---------------- helpers ----------------
__device__ __forceinline__ float tanhapx(float x) {
    float r; asm("tanh.approx.f32 %0, %1;" : "=f"(r) : "f"(x)); return r;
}
__device__ __forceinline__ float sigf(float x) {
    return 0.5f + 0.5f * tanhapx(0.5f * x);
}
__device__ __forceinline__ void cp16(void* smem, const void* gmem) {
    uint32_t s = (uint32_t)__cvta_generic_to_shared(smem);
    asm volatile("cp.async.cg.shared.global [%0], [%1], 16;\n" :: "r"(s), "l"(gmem) : "memory");
}
__device__ __forceinline__ void cp_commit() {
    asm volatile("cp.async.commit_group;\n" ::: "memory");
}
template<int N> __device__ __forceinline__ void cp_wait() {
    asm volatile("cp.async.wait_group %0;\n" :: "n"(N) : "memory");
}

// ---------------- K1: embedding gather -> bf16, K-padded (vectorized) ----------------
__global__ void k_prep_emb(const int* __restrict__ x, const float* __restrict__ embed) {
    const int row = blockIdx.x;          // 0..65535
    const int p   = threadIdx.x;         // 0..159 (pair index)
    const int xv  = x[row];
    __nv_bfloat162 v;
    if (p < E_ / 2) {
        float2 f = *(const float2*)&embed[(size_t)xv * E_ + p * 2];
        v = __floats2bfloat162_rn(f.x, f.y);
    } else {
        v = __floats2bfloat162_rn(0.0f, 0.0f);
    }
    *(__nv_bfloat162*)&g_emb[(size_t)row * KP + p * 2] = v;
}

// ---------------- K1b: weight packing ----------------
__global__ void k_prep_w(const float* __restrict__ Wih_f, const float* __restrict__ Whh_f,
                         const float* __restrict__ b_f,
                         const float* __restrict__ Wih_b, const float* __restrict__ Whh_b,
                         const float* __restrict__ b_b) {
    int idx = blockIdx.x * blockDim.x + threadIdx.x;
    const int NW = 1024 * KP;
    const int NH = 2 * G4 * H_;
    if (idx < NW) {
        int r = idx / KP, k = idx % KP;
        float v = 0.0f;
        if (k < E_) v = (r < G4) ? Wih_f[r * E_ + k] : Wih_b[(r - G4) * E_ + k];
        g_wcat[idx] = __float2bfloat16(v);
    } else if (idx < NW + NH) {
        int i = idx - NW;
        int d = i / (G4 * H_);
        int rem = i % (G4 * H_);
        float v = d ? Whh_b[rem] : Whh_f[rem];
        g_whh[i] = __float2bfloat16(v);
    } else if (idx < NW + NH + 1024) {
        int n = idx - NW - NH;
        g_bias[n] = (n < G4) ? b_f[n] : b_b[n - G4];
    }
}

// ---------------- K2: input GEMM (bf16 mma.sync + ldmatrix, cp.async 3-stage) ----------------
#define BM 128
#define BN 64
#define BK 32
#define SA 40
#define KITERS (KP / BK)   // 10
#define NSTG 3

__global__ __launch_bounds__(256) void k_gemm_in() {
    __shared__ __align__(16) __nv_bfloat16 As[NSTG][BM * SA];
    __shared__ __align__(16) __nv_bfloat16 Bs[NSTG][BN * SA];
    const int m0 = blockIdx.y * BM;
    const int n0 = blockIdx.x * BN;
    const int tid = threadIdx.x;
    const int warp = tid >> 5, lane = tid & 31;
    const int wm = warp >> 1, wn = warp & 1;   // 4x2 warp grid, warp tile 32x32

    float acc[2][4][4];
    #pragma unroll
    for (int a = 0; a < 2; a++)
        #pragma unroll
        for (int b = 0; b < 4; b++)
            #pragma unroll
            for (int c = 0; c < 4; c++) acc[a][b][c] = 0.0f;

    const int lr = lane >> 2, lc = (lane & 3) * 2;
    const int ldr = tid >> 2, seg = tid & 3;
    const int lg = lane >> 3, lr8 = lane & 7;   // ldmatrix lane decomposition

    // per-stage ldmatrix base addresses (byte offsets into shared)
    uint32_t aAddr[NSTG][2], bAddr[NSTG][2];
    #pragma unroll
    for (int st = 0; st < NSTG; st++) {
        #pragma unroll
        for (int mi = 0; mi < 2; mi++) {
            const int arow = wm * 32 + mi * 16 + lr8 + (lg & 1) * 8;
            const int acol = (lg >> 1) * 8;
            aAddr[st][mi] = (uint32_t)__cvta_generic_to_shared(
                &As[st][arow * SA + acol]);
        }
        #pragma unroll
        for (int kh = 0; kh < 2; kh++) {
            const int brow = wn * 32 + lg * 8 + lr8;
            bAddr[st][kh] = (uint32_t)__cvta_generic_to_shared(
                &Bs[st][brow * SA + kh * 8]);
        }
    }

    #pragma unroll
    for (int p = 0; p < 2; p++) {
        const int kt = p * BK;
        cp16(&As[p][ldr * SA + seg * 8],        &g_emb[(size_t)(m0 + ldr) * KP + kt + seg * 8]);
        cp16(&As[p][(ldr + 64) * SA + seg * 8], &g_emb[(size_t)(m0 + ldr + 64) * KP + kt + seg * 8]);
        cp16(&Bs[p][ldr * SA + seg * 8],        &g_wcat[(size_t)(n0 + ldr) * KP + kt + seg * 8]);
        cp_commit();
    }

    for (int it = 0; it < KITERS; it++) {
        if (it + 2 < KITERS) {
            const int kt = (it + 2) * BK;
            const int st = (it + 2) % NSTG;
            cp16(&As[st][ldr * SA + seg * 8],        &g_emb[(size_t)(m0 + ldr) * KP + kt + seg * 8]);
            cp16(&As[st][(ldr + 64) * SA + seg * 8], &g_emb[(size_t)(m0 + ldr + 64) * KP + kt + seg * 8]);
            cp16(&Bs[st][ldr * SA + seg * 8],        &g_wcat[(size_t)(n0 + ldr) * KP + kt + seg * 8]);
            cp_commit();
            cp_wait<2>();
        } else if (it + 1 < KITERS) {
            cp_wait<1>();
        } else {
            cp_wait<0>();
        }
        __syncthreads();
        const int st = it % NSTG;
        #pragma unroll
        for (int ks = 0; ks < 2; ks++) {
            const uint32_t koff = (uint32_t)(ks * 16) * 2;   // bytes
            uint32_t a[2][4];
            #pragma unroll
            for (int mi = 0; mi < 2; mi++)
                asm volatile("ldmatrix.sync.aligned.m8n8.x4.shared.b16 {%0,%1,%2,%3}, [%4];\n"
                             : "=r"(a[mi][0]), "=r"(a[mi][1]), "=r"(a[mi][2]), "=r"(a[mi][3])
                             : "r"(aAddr[st][mi] + koff));
            uint32_t bfr[4][2];
            #pragma unroll
            for (int kh = 0; kh < 2; kh++)
                asm volatile("ldmatrix.sync.aligned.m8n8.x4.shared.b16 {%0,%1,%2,%3}, [%4];\n"
                             : "=r"(bfr[0][kh]), "=r"(bfr[1][kh]), "=r"(bfr[2][kh]), "=r"(bfr[3][kh])
                             : "r"(bAddr[st][kh] + koff));
            #pragma unroll
            for (int mi = 0; mi < 2; mi++)
                #pragma unroll
                for (int ni = 0; ni < 4; ni++) {
                    asm volatile(
                        "mma.sync.aligned.m16n8k16.row.col.f32.bf16.bf16.f32 "
                        "{%0,%1,%2,%3}, {%4,%5,%6,%7}, {%8,%9}, {%0,%1,%2,%3};\n"
                        : "+f"(acc[mi][ni][0]), "+f"(acc[mi][ni][1]),
                          "+f"(acc[mi][ni][2]), "+f"(acc[mi][ni][3])
                        : "r"(a[mi][0]), "r"(a[mi][1]), "r"(a[mi][2]), "r"(a[mi][3]),
                          "r"(bfr[ni][0]), "r"(bfr[ni][1]));
                }
        }
        __syncthreads();
    }
    // epilogue: add bias, scatter fp32 to PRE[d][b][s][j]
    #pragma unroll
    for (int mi = 0; mi < 2; mi++) {
        #pragma unroll
        for (int ni = 0; ni < 4; ni++) {
            int m = m0 + wm * 32 + mi * 16 + lr;
            int n = n0 + wn * 32 + ni * 8 + lc;
            int d = n >> 9, j = n & 511;
            float bias0 = g_bias[n], bias1 = g_bias[n + 1];
            {
                int bb = m >> 9, ss = m & 511;
                size_t base = (((size_t)(d * B_ + bb) * S_ + ss) * G4 + j);
                *(float2*)&g_pre[base] = make_float2(acc[mi][ni][0] + bias0,
                                                     acc[mi][ni][1] + bias1);
            }
            {
                int m2 = m + 8;
                int bb = m2 >> 9, ss = m2 & 511;
                size_t base = (((size_t)(d * B_ + bb) * S_ + ss) * G4 + j);
                *(float2*)&g_pre[base] = make_float2(acc[mi][ni][2] + bias0,
                                                     acc[mi][ni][3] + bias1);
            }
        }
    }
}

// ---------------- K3: tensor-core recurrence (R4-proven config) ----------------
// 32 blocks = (dir, 8-batch group). 512 threads = 16 warps.
// Warp w: its 4 n8-tiles are gates {w*8 + ni*128} -> i,f,g,o for 2 cells in regs.
// fp32 PRE prefetch (pointer-stepped), bf16 h_sm + hcat, 1 barrier/step.
#define HS 136   // h_sm row stride in bf16 (272B -> conflict-free ldmatrix)

__global__ __launch_bounds__(512, 1) void k_lstm() {
    __shared__ __align__(16) __nv_bfloat16 h_sm[2][16][HS];

    const int d   = blockIdx.x >> 4;
    const int bg  = blockIdx.x & 15;
    const int b0  = bg * 8;
    const int tid = threadIdx.x;
    const int w = tid >> 5, l = tid & 31;
    const int r = l >> 2, cpair = (l & 3) * 2;

    // preload B fragments (Whh) once: 64 regs
    uint32_t Bf[4][8][2];
    #pragma unroll
    for (int ni = 0; ni < 4; ni++) {
        const int n = w * 8 + ni * 128 + r;
        const __nv_bfloat16* src = &g_whh[((size_t)d * G4 + n) * H_ + cpair];
        #pragma unroll
        for (int tk = 0; tk < 8; tk++) {
            Bf[ni][tk][0] = *(const uint32_t*)&src[tk * 16];
            Bf[ni][tk][1] = *(const uint32_t*)&src[tk * 16 + 8];
        }
    }
    // zero both h buffers (rows 8-15 stay zero = M padding)
    for (int i = tid; i < 2 * 16 * HS; i += 512)
        ((__nv_bfloat16*)h_sm)[i] = __float2bfloat16(0.0f);

    const int b  = b0 + r;
    const int m0 = w * 8 + cpair;
    const int sgn = d ? -1 : 1;
    const int se0 = d ? (S_ - 1) : 0;

    const float* preb = &g_pre[((size_t)(d * B_ + b) * S_ + se0) * G4 + m0];
    __nv_bfloat16* hout = &g_hcat[((size_t)b * S_ + se0) * 256 + d * H_ + m0];
    const int preb_step = sgn * G4;
    const int hout_step = sgn * 256;

    float2 pf[4];
    #pragma unroll
    for (int ni = 0; ni < 4; ni++)
        pf[ni] = *(const float2*)&preb[ni * 128];

    float cA = 0.0f, cB = 0.0f;
    const uint32_t abase0 =
        (uint32_t)__cvta_generic_to_shared(&h_sm[0][l & 15][(l >> 4) * 8]);

    __syncthreads();

    int buf = 0;
    #pragma unroll 1
    for (int s = 0; s < S_; s++) {
        // acc init = current pre-activations (bias folded in)
        float acc[4][4];
        #pragma unroll
        for (int ni = 0; ni < 4; ni++) {
            acc[ni][0] = pf[ni].x; acc[ni][1] = pf[ni].y;
            acc[ni][2] = 0.0f;     acc[ni][3] = 0.0f;
        }
        // prefetch next step (pointer increment; last iter re-reads current)
        if (s < S_ - 1) preb += preb_step;
        #pragma unroll
        for (int ni = 0; ni < 4; ni++)
            pf[ni] = *(const float2*)&preb[ni * 128];

        const uint32_t abase = abase0 + (uint32_t)buf * (16 * HS * 2);
        #pragma unroll
        for (int tk = 0; tk < 8; tk++) {
            uint32_t a0, a1, a2, a3;
            asm volatile("ldmatrix.sync.aligned.m8n8.x4.shared.b16 {%0,%1,%2,%3}, [%4];\n"
                         : "=r"(a0), "=r"(a1), "=r"(a2), "=r"(a3)
                         : "r"(abase + tk * 32));
            #pragma unroll
            for (int ni = 0; ni < 4; ni++) {
                asm volatile(
                    "mma.sync.aligned.m16n8k16.row.col.f32.bf16.bf16.f32 "
                    "{%0,%1,%2,%3}, {%4,%5,%6,%7}, {%8,%9}, {%0,%1,%2,%3};\n"
                    : "+f"(acc[ni][0]), "+f"(acc[ni][1]),
                      "+f"(acc[ni][2]), "+f"(acc[ni][3])
                    : "r"(a0), "r"(a1), "r"(a2), "r"(a3),
                      "r"(Bf[ni][tk][0]), "r"(Bf[ni][tk][1]));
            }
        }

        // gates: ni 0=i, 1=f, 2=g, 3=o ; 2 cells (m0, m0+1), batch b
        cA = sigf(acc[1][0]) * cA + sigf(acc[0][0]) * tanhapx(acc[2][0]);
        cB = sigf(acc[1][1]) * cB + sigf(acc[0][1]) * tanhapx(acc[2][1]);
        float hA = sigf(acc[3][0]) * tanhapx(cA);
        float hB = sigf(acc[3][1]) * tanhapx(cB);

        __nv_bfloat162 hpk = __floats2bfloat162_rn(hA, hB);
        *(__nv_bfloat162*)&h_sm[buf ^ 1][r][m0] = hpk;
        *(__nv_bfloat162*)hout = hpk;
        hout += hout_step;

        __syncthreads();
        buf ^= 1;
    }
}

// ---------------- K4: output linear (bf16 hcat) ----------------
__global__ void k_out(const float* __restrict__ Wout, const float* __restrict__ bout) {
    const int lr = threadIdx.x >> 4;
    const int t  = threadIdx.x & 15;
    const int row = blockIdx.x * 16 + lr;
    if (t >= T_) return;
    float acc = bout[t];
    const __nv_bfloat162* hv = (const __nv_bfloat162*)&g_hcat[(size_t)row * 256];
    const float2* wv = (const float2*)&Wout[t * 256];
    #pragma unroll 16
    for (int q = 0; q < 128; q++) {
        float2 h2 = __bfloat1622float2(hv[q]);
        float2 w2 = wv[q];
        acc += h2.x * w2.x + h2.y * w2.y;
    }
    g_y[(size_t)row * T_ + t] = acc;
}

// ---------------- K5: CRF forward + gold ----------------
__global__ void k_crf(const int* __restrict__ y0, const float* __restrict__ trans,
                      float* __restrict__ out) {
    __shared__ float tsm[T_ * T_];
    const int b = blockIdx.x;
    const int lane = threadIdx.x;
    for (int i = lane; i < T_ * T_; i += 32) tsm[i] = trans[i];
    __syncwarp();

    float trow[T_];
    const int irow = (lane < T_) ? lane : 0;
    #pragma unroll
    for (int jj = 0; jj < T_; jj++) trow[jj] = tsm[irow * T_ + jj];

    float score = (lane == SOS_) ? 0.0f : NEGV;
    const float* gyb = &g_y[(size_t)b * S_ * T_];

    float yv_next = (lane < T_) ? gyb[lane] : 0.0f;
    for (int s = 0; s < S_; s++) {
        float yv = yv_next;
        if (s + 1 < S_)
            yv_next = (lane < T_) ? gyb[(s + 1) * T_ + lane] : 0.0f;
        float v[T_];
        float mx = -1e30f;
        #pragma unroll
        for (int jj = 0; jj < T_; jj++) {
            float sj = __shfl_sync(0xffffffffu, score, jj);
            v[jj] = sj + trow[jj];
            mx = fmaxf(mx, v[jj]);
        }
        float sum = 0.0f;
        #pragma unroll
        for (int jj = 0; jj < T_; jj++) sum += __expf(v[jj] - mx);
        score = mx + __logf(sum) + yv;
    }
    float vz = (lane < T_) ? score + tsm[EOS_ * T_ + lane] : -1e30f;
    float mz = vz;
    #pragma unroll
    for (int o = 16; o; o >>= 1) mz = fmaxf(mz, __shfl_xor_sync(0xffffffffu, mz, o));
    float ez = (lane < T_) ? __expf(vz - mz) : 0.0f;
    #pragma unroll
    for (int o = 16; o; o >>= 1) ez += __shfl_xor_sync(0xffffffffu, ez, o);
    float Z = mz + __logf(ez);

    const int* yb = &y0[b * S_];
    float g = 0.0f;
    for (int s = lane; s < S_; s += 32) {
        int cur = yb[s];
        int prev = s ? yb[s - 1] : SOS_;
        g += gyb[s * T_ + cur] + tsm[cur * T_ + prev];
    }
    #pragma unroll
    for (int o = 16; o; o >>= 1) g += __shfl_xor_sync(0xffffffffu, g, o);
    if (lane == 0) {
        g += tsm[EOS_ * T_ + yb[S_ - 1]];
        out[b] = Z - g;
    }
}

// ---------------- launcher ----------------
extern "C" void kernel_launch(void* const* d_in, const int* in_sizes, int n_in,
                              void* d_out, int out_size) {
    const int*   x     = (const int*)d_in[0];
    const int*   y0    = (const int*)d_in[1];
    const float* embed = (const float*)d_in[2];
    const float* Wih_f = (const float*)d_in[3];
    const float* Whh_f = (const float*)d_in[4];
    const float* b_f   = (const float*)d_in[5];
    const float* Wih_b = (const float*)d_in[6];
    const float* Whh_b = (const float*)d_in[7];
    const float* b_b   = (const float*)d_in[8];
    const float* Wout  = (const float*)d_in[9];
    const float* bout  = (const float*)d_in[10];
    const float* trans = (const float*)d_in[11];
    float* out = (float*)d_out;

    k_prep_emb<<<B_ * S_, KP / 2>>>(x, embed);

    const int prep_total = 1024 * KP + 2 * G4 * H_ + 1024;
    k_prep_w<<<(prep_total + 255) / 256, 256>>>(Wih_f, Whh_f, b_f, Wih_b, Whh_b, b_b);

    dim3 gg(1024 / BN, (B_ * S_) / BM);
    k_gemm_in<<<gg, 256>>>();

    k_lstm<<<32, 512>>>();

    k_out<<<(B_ * S_) / 16, 256>>>(Wout, bout);

    k_crf<<<B_, 32>>>(y0, trans, out);
}

// round 10
// speedup vs baseline: 1.3496x; 1.1625x over previous
#include <cuda_runtime.h>
#include <cuda_bf16.h>
#include <cstdint>

#define B_   128
#define S_   512
#define E_   300
#define KP   320     // padded K for GEMM
#define H_   128
#define G4   512     // 4*H
#define T_   12
#define SOS_ 3
#define EOS_ 4
#define NEGV (-10000.0f)

// ---------------- scratch (static device allocations) ----------------
__device__ __align__(16) __nv_bfloat16 g_emb[(size_t)B_*S_*KP];   // [65536][320]
__device__ __align__(16) __nv_bfloat16 g_wcat[1024*KP];           // [1024][320]
__device__ __align__(16) __nv_bfloat16 g_whh[2*G4*H_];            // [2][512][128]
__device__ float g_bias[1024];
__device__ float g_pre[(size_t)2*B_*S_*G4];                       // [2][128][512][512] fp32
__device__ __align__(16) __nv_bfloat16 g_hcat[(size_t)B_*S_*2*H_]; // [65536][256] bf16

// ---------------- helpers ----------------
__device__ __forceinline__ float tanhapx(float x) {
    float r; asm("tanh.approx.f32 %0, %1;" : "=f"(r) : "f"(x)); return r;
}
__device__ __forceinline__ float sigf(float x) {
    return 0.5f + 0.5f * tanhapx(0.5f * x);
}
__device__ __forceinline__ void cp16(void* smem, const void* gmem) {
    uint32_t s = (uint32_t)__cvta_generic_to_shared(smem);
    asm volatile("cp.async.cg.shared.global [%0], [%1], 16;\n" :: "r"(s), "l"(gmem) : "memory");
}
__device__ __forceinline__ void cp_commit() {
    asm volatile("cp.async.commit_group;\n" ::: "memory");
}
template<int N> __device__ __forceinline__ void cp_wait() {
    asm volatile("cp.async.wait_group %0;\n" :: "n"(N) : "memory");
}

// ---------------- K1: embedding gather -> bf16, K-padded (vectorized) ----------------
__global__ void k_prep_emb(const int* __restrict__ x, const float* __restrict__ embed) {
    const int row = blockIdx.x;          // 0..65535
    const int p   = threadIdx.x;         // 0..159 (pair index)
    const int xv  = x[row];
    __nv_bfloat162 v;
    if (p < E_ / 2) {
        float2 f = *(const float2*)&embed[(size_t)xv * E_ + p * 2];
        v = __floats2bfloat162_rn(f.x, f.y);
    } else {
        v = __floats2bfloat162_rn(0.0f, 0.0f);
    }
    *(__nv_bfloat162*)&g_emb[(size_t)row * KP + p * 2] = v;
}

// ---------------- K1b: weight packing ----------------
__global__ void k_prep_w(const float* __restrict__ Wih_f, const float* __restrict__ Whh_f,
                         const float* __restrict__ b_f,
                         const float* __restrict__ Wih_b, const float* __restrict__ Whh_b,
                         const float* __restrict__ b_b) {
    int idx = blockIdx.x * blockDim.x + threadIdx.x;
    const int NW = 1024 * KP;
    const int NH = 2 * G4 * H_;
    if (idx < NW) {
        int r = idx / KP, k = idx % KP;
        float v = 0.0f;
        if (k < E_) v = (r < G4) ? Wih_f[r * E_ + k] : Wih_b[(r - G4) * E_ + k];
        g_wcat[idx] = __float2bfloat16(v);
    } else if (idx < NW + NH) {
        int i = idx - NW;
        int d = i / (G4 * H_);
        int rem = i % (G4 * H_);
        float v = d ? Whh_b[rem] : Whh_f[rem];
        g_whh[i] = __float2bfloat16(v);
    } else if (idx < NW + NH + 1024) {
        int n = idx - NW - NH;
        g_bias[n] = (n < G4) ? b_f[n] : b_b[n - G4];
    }
}

// ---------------- K2: input GEMM (bf16 mma.sync + ldmatrix, cp.async 3-stage) ----------------
#define BM 128
#define BN 64
#define BK 32
#define SA 40
#define KITERS (KP / BK)   // 10
#define NSTG 3

__global__ __launch_bounds__(256) void k_gemm_in() {
    __shared__ __align__(16) __nv_bfloat16 As[NSTG][BM * SA];
    __shared__ __align__(16) __nv_bfloat16 Bs[NSTG][BN * SA];
    const int m0 = blockIdx.y * BM;
    const int n0 = blockIdx.x * BN;
    const int tid = threadIdx.x;
    const int warp = tid >> 5, lane = tid & 31;
    const int wm = warp >> 1, wn = warp & 1;   // 4x2 warp grid, warp tile 32x32

    float acc[2][4][4];
    #pragma unroll
    for (int a = 0; a < 2; a++)
        #pragma unroll
        for (int b = 0; b < 4; b++)
            #pragma unroll
            for (int c = 0; c < 4; c++) acc[a][b][c] = 0.0f;

    const int lr = lane >> 2, lc = (lane & 3) * 2;
    const int ldr = tid >> 2, seg = tid & 3;
    const int lg = lane >> 3, lr8 = lane & 7;   // ldmatrix lane decomposition

    uint32_t aAddr[NSTG][2], bAddr[NSTG][2];
    #pragma unroll
    for (int st = 0; st < NSTG; st++) {
        #pragma unroll
        for (int mi = 0; mi < 2; mi++) {
            const int arow = wm * 32 + mi * 16 + lr8 + (lg & 1) * 8;
            const int acol = (lg >> 1) * 8;
            aAddr[st][mi] = (uint32_t)__cvta_generic_to_shared(
                &As[st][arow * SA + acol]);
        }
        #pragma unroll
        for (int kh = 0; kh < 2; kh++) {
            const int brow = wn * 32 + lg * 8 + lr8;
            bAddr[st][kh] = (uint32_t)__cvta_generic_to_shared(
                &Bs[st][brow * SA + kh * 8]);
        }
    }

    #pragma unroll
    for (int p = 0; p < 2; p++) {
        const int kt = p * BK;
        cp16(&As[p][ldr * SA + seg * 8],        &g_emb[(size_t)(m0 + ldr) * KP + kt + seg * 8]);
        cp16(&As[p][(ldr + 64) * SA + seg * 8], &g_emb[(size_t)(m0 + ldr + 64) * KP + kt + seg * 8]);
        cp16(&Bs[p][ldr * SA + seg * 8],        &g_wcat[(size_t)(n0 + ldr) * KP + kt + seg * 8]);
        cp_commit();
    }

    for (int it = 0; it < KITERS; it++) {
        if (it + 2 < KITERS) {
            const int kt = (it + 2) * BK;
            const int st = (it + 2) % NSTG;
            cp16(&As[st][ldr * SA + seg * 8],        &g_emb[(size_t)(m0 + ldr) * KP + kt + seg * 8]);
            cp16(&As[st][(ldr + 64) * SA + seg * 8], &g_emb[(size_t)(m0 + ldr + 64) * KP + kt + seg * 8]);
            cp16(&Bs[st][ldr * SA + seg * 8],        &g_wcat[(size_t)(n0 + ldr) * KP + kt + seg * 8]);
            cp_commit();
            cp_wait<2>();
        } else if (it + 1 < KITERS) {
            cp_wait<1>();
        } else {
            cp_wait<0>();
        }
        __syncthreads();
        const int st = it % NSTG;
        #pragma unroll
        for (int ks = 0; ks < 2; ks++) {
            const uint32_t koff = (uint32_t)(ks * 16) * 2;   // bytes
            uint32_t a[2][4];
            #pragma unroll
            for (int mi = 0; mi < 2; mi++)
                asm volatile("ldmatrix.sync.aligned.m8n8.x4.shared.b16 {%0,%1,%2,%3}, [%4];\n"
                             : "=r"(a[mi][0]), "=r"(a[mi][1]), "=r"(a[mi][2]), "=r"(a[mi][3])
                             : "r"(aAddr[st][mi] + koff));
            uint32_t bfr[4][2];
            #pragma unroll
            for (int kh = 0; kh < 2; kh++)
                asm volatile("ldmatrix.sync.aligned.m8n8.x4.shared.b16 {%0,%1,%2,%3}, [%4];\n"
                             : "=r"(bfr[0][kh]), "=r"(bfr[1][kh]), "=r"(bfr[2][kh]), "=r"(bfr[3][kh])
                             : "r"(bAddr[st][kh] + koff));
            #pragma unroll
            for (int mi = 0; mi < 2; mi++)
                #pragma unroll
                for (int ni = 0; ni < 4; ni++) {
                    asm volatile(
                        "mma.sync.aligned.m16n8k16.row.col.f32.bf16.bf16.f32 "
                        "{%0,%1,%2,%3}, {%4,%5,%6,%7}, {%8,%9}, {%0,%1,%2,%3};\n"
                        : "+f"(acc[mi][ni][0]), "+f"(acc[mi][ni][1]),
                          "+f"(acc[mi][ni][2]), "+f"(acc[mi][ni][3])
                        : "r"(a[mi][0]), "r"(a[mi][1]), "r"(a[mi][2]), "r"(a[mi][3]),
                          "r"(bfr[ni][0]), "r"(bfr[ni][1]));
                }
        }
        __syncthreads();
    }
    // epilogue: add bias, scatter fp32 to PRE[d][b][s][j]
    #pragma unroll
    for (int mi = 0; mi < 2; mi++) {
        #pragma unroll
        for (int ni = 0; ni < 4; ni++) {
            int m = m0 + wm * 32 + mi * 16 + lr;
            int n = n0 + wn * 32 + ni * 8 + lc;
            int d = n >> 9, j = n & 511;
            float bias0 = g_bias[n], bias1 = g_bias[n + 1];
            {
                int bb = m >> 9, ss = m & 511;
                size_t base = (((size_t)(d * B_ + bb) * S_ + ss) * G4 + j);
                *(float2*)&g_pre[base] = make_float2(acc[mi][ni][0] + bias0,
                                                     acc[mi][ni][1] + bias1);
            }
            {
                int m2 = m + 8;
                int bb = m2 >> 9, ss = m2 & 511;
                size_t base = (((size_t)(d * B_ + bb) * S_ + ss) * G4 + j);
                *(float2*)&g_pre[base] = make_float2(acc[mi][ni][2] + bias0,
                                                     acc[mi][ni][3] + bias1);
            }
        }
    }
}

// ---------------- K3: tensor-core recurrence (proven config) ----------------
#define HS 136   // h_sm row stride in bf16 (272B -> conflict-free ldmatrix)

__global__ __launch_bounds__(512, 1) void k_lstm() {
    __shared__ __align__(16) __nv_bfloat16 h_sm[2][16][HS];

    const int d   = blockIdx.x >> 4;
    const int bg  = blockIdx.x & 15;
    const int b0  = bg * 8;
    const int tid = threadIdx.x;
    const int w = tid >> 5, l = tid & 31;
    const int r = l >> 2, cpair = (l & 3) * 2;

    uint32_t Bf[4][8][2];
    #pragma unroll
    for (int ni = 0; ni < 4; ni++) {
        const int n = w * 8 + ni * 128 + r;
        const __nv_bfloat16* src = &g_whh[((size_t)d * G4 + n) * H_ + cpair];
        #pragma unroll
        for (int tk = 0; tk < 8; tk++) {
            Bf[ni][tk][0] = *(const uint32_t*)&src[tk * 16];
            Bf[ni][tk][1] = *(const uint32_t*)&src[tk * 16 + 8];
        }
    }
    for (int i = tid; i < 2 * 16 * HS; i += 512)
        ((__nv_bfloat16*)h_sm)[i] = __float2bfloat16(0.0f);

    const int b  = b0 + r;
    const int m0 = w * 8 + cpair;
    const int sgn = d ? -1 : 1;
    const int se0 = d ? (S_ - 1) : 0;

    const float* preb = &g_pre[((size_t)(d * B_ + b) * S_ + se0) * G4 + m0];
    __nv_bfloat16* hout = &g_hcat[((size_t)b * S_ + se0) * 256 + d * H_ + m0];
    const int preb_step = sgn * G4;
    const int hout_step = sgn * 256;

    float2 pf[4];
    #pragma unroll
    for (int ni = 0; ni < 4; ni++)
        pf[ni] = *(const float2*)&preb[ni * 128];

    float cA = 0.0f, cB = 0.0f;
    const uint32_t abase0 =
        (uint32_t)__cvta_generic_to_shared(&h_sm[0][l & 15][(l >> 4) * 8]);

    __syncthreads();

    int buf = 0;
    #pragma unroll 1
    for (int s = 0; s < S_; s++) {
        float acc[4][4];
        #pragma unroll
        for (int ni = 0; ni < 4; ni++) {
            acc[ni][0] = pf[ni].x; acc[ni][1] = pf[ni].y;
            acc[ni][2] = 0.0f;     acc[ni][3] = 0.0f;
        }
        if (s < S_ - 1) preb += preb_step;
        #pragma unroll
        for (int ni = 0; ni < 4; ni++)
            pf[ni] = *(const float2*)&preb[ni * 128];

        const uint32_t abase = abase0 + (uint32_t)buf * (16 * HS * 2);
        #pragma unroll
        for (int tk = 0; tk < 8; tk++) {
            uint32_t a0, a1, a2, a3;
            asm volatile("ldmatrix.sync.aligned.m8n8.x4.shared.b16 {%0,%1,%2,%3}, [%4];\n"
                         : "=r"(a0), "=r"(a1), "=r"(a2), "=r"(a3)
                         : "r"(abase + tk * 32));
            #pragma unroll
            for (int ni = 0; ni < 4; ni++) {
                asm volatile(
                    "mma.sync.aligned.m16n8k16.row.col.f32.bf16.bf16.f32 "
                    "{%0,%1,%2,%3}, {%4,%5,%6,%7}, {%8,%9}, {%0,%1,%2,%3};\n"
                    : "+f"(acc[ni][0]), "+f"(acc[ni][1]),
                      "+f"(acc[ni][2]), "+f"(acc[ni][3])
                    : "r"(a0), "r"(a1), "r"(a2), "r"(a3),
                      "r"(Bf[ni][tk][0]), "r"(Bf[ni][tk][1]));
            }
        }

        cA = sigf(acc[1][0]) * cA + sigf(acc[0][0]) * tanhapx(acc[2][0]);
        cB = sigf(acc[1][1]) * cB + sigf(acc[0][1]) * tanhapx(acc[2][1]);
        float hA = sigf(acc[3][0]) * tanhapx(cA);
        float hB = sigf(acc[3][1]) * tanhapx(cB);

        __nv_bfloat162 hpk = __floats2bfloat162_rn(hA, hB);
        *(__nv_bfloat162*)&h_sm[buf ^ 1][r][m0] = hpk;
        *(__nv_bfloat162*)hout = hpk;
        hout += hout_step;

        __syncthreads();
        buf ^= 1;
    }
}

// ---------------- K4: fused output linear + CRF forward + gold ----------------
// 128 blocks (one per batch), 128 threads.
// Phase 1 (all): y[512][12] into smem from hcat@Wout^T + bout.
// Phase 2: warp 0 = exp-domain forward scan; warps 1-3 = gold score.
__global__ __launch_bounds__(128) void k_outcrf(const int* __restrict__ y0,
                                                const float* __restrict__ trans,
                                                const float* __restrict__ Wout,
                                                const float* __restrict__ bout,
                                                float* __restrict__ out) {
    __shared__ float ysm[S_][T_];        // 24576 B
    __shared__ float wsm[T_][256];       // 12288 B
    __shared__ float tsm[T_][T_];
    __shared__ float esm[T_][T_];
    __shared__ float gpart[3];
    __shared__ float zsm;

    const int b = blockIdx.x;
    const int tid = threadIdx.x;
    const int lane = tid & 31, wrp = tid >> 5;

    // load Wout (12x256) and trans (12x12 = 144 > 128 threads -> strided!), build exp(trans)
    for (int i = tid; i < T_ * 256; i += 128) wsm[0][i] = Wout[i];
    for (int i = tid; i < T_ * T_; i += 128) {
        float tv = trans[i];
        tsm[0][i] = tv;
        esm[0][i] = __expf(tv);    // exp(-1e4) = 0 exactly
    }
    if (tid < 3) gpart[tid] = 0.0f;
    __syncthreads();

    // ---- Phase 1: y = hcat @ Wout^T + bout ----
    const __nv_bfloat162* hbase = (const __nv_bfloat162*)&g_hcat[(size_t)b * S_ * 256];
    for (int idx = tid; idx < S_ * T_; idx += 128) {
        const int s = idx / T_, t = idx - s * T_;
        const __nv_bfloat162* hp = hbase + s * 128;
        const float2* wp = (const float2*)&wsm[t][0];
        float acc = bout[t];
        #pragma unroll 16
        for (int q = 0; q < 128; q++) {
            float2 h2 = __bfloat1622float2(hp[q]);
            float2 w2 = wp[q];
            acc += h2.x * w2.x + h2.y * w2.y;
        }
        ysm[s][t] = acc;
    }
    __syncthreads();

    // ---- Phase 2a: warps 1-3 compute gold path score ----
    if (wrp > 0) {
        const int* yb = &y0[b * S_];
        float g = 0.0f;
        for (int s = tid - 32; s < S_; s += 96) {
            int cur = yb[s];
            int prev = s ? yb[s - 1] : SOS_;
            g += ysm[s][cur] + tsm[cur][prev];
        }
        #pragma unroll
        for (int o = 16; o; o >>= 1) g += __shfl_xor_sync(0xffffffffu, g, o);
        if (lane == 0) gpart[wrp - 1] = g;
    }
    // ---- Phase 2b: warp 0 forward scan (exp-domain, lane-0 anchor) ----
    else {
        float e_row[T_];
        const int irow = (lane < T_) ? lane : 0;
        #pragma unroll
        for (int jj = 0; jj < T_; jj++) e_row[jj] = esm[irow][jj];

        // step 0 exact: score1_i = trans[i][SOS] + y[0][i]
        float score = (lane < T_) ? tsm[irow][SOS_] + ysm[0][irow] : -1e30f;

        for (int s = 1; s < S_; s++) {
            float anchor = __shfl_sync(0xffffffffu, score, 0);
            float p = __expf(score - anchor);        // lanes>=12 -> 0
            float Ssum = 0.0f;
            #pragma unroll
            for (int jj = 0; jj < T_; jj++)
                Ssum = fmaf(e_row[jj], __shfl_sync(0xffffffffu, p, jj), Ssum);
            float yv = ysm[s][irow];
            score = (lane < T_) ? anchor + __logf(Ssum) + yv : -1e30f;
        }
        // Z = lse_i(score_i + trans[EOS][i]) with full max tree (once)
        float vz = (lane < T_) ? score + tsm[EOS_][irow] : -1e30f;
        float mz = vz;
        #pragma unroll
        for (int o = 16; o; o >>= 1) mz = fmaxf(mz, __shfl_xor_sync(0xffffffffu, mz, o));
        float ez = (lane < T_) ? __expf(vz - mz) : 0.0f;
        #pragma unroll
        for (int o = 16; o; o >>= 1) ez += __shfl_xor_sync(0xffffffffu, ez, o);
        if (lane == 0) zsm = mz + __logf(ez);
    }
    __syncthreads();
    if (tid == 0) {
        const int last = y0[b * S_ + S_ - 1];
        float gold = gpart[0] + gpart[1] + gpart[2] + tsm[EOS_][last];
        out[b] = zsm - gold;
    }
}

// ---------------- launcher ----------------
extern "C" void kernel_launch(void* const* d_in, const int* in_sizes, int n_in,
                              void* d_out, int out_size) {
    const int*   x     = (const int*)d_in[0];
    const int*   y0    = (const int*)d_in[1];
    const float* embed = (const float*)d_in[2];
    const float* Wih_f = (const float*)d_in[3];
    const float* Whh_f = (const float*)d_in[4];
    const float* b_f   = (const float*)d_in[5];
    const float* Wih_b = (const float*)d_in[6];
    const float* Whh_b = (const float*)d_in[7];
    const float* b_b   = (const float*)d_in[8];
    const float* Wout  = (const float*)d_in[9];
    const float* bout  = (const float*)d_in[10];
    const float* trans = (const float*)d_in[11];
    float* out = (float*)d_out;

    k_prep_emb<<<B_ * S_, KP / 2>>>(x, embed);

    const int prep_total = 1024 * KP + 2 * G4 * H_ + 1024;
    k_prep_w<<<(prep_total + 255) / 256, 256>>>(Wih_f, Whh_f, b_f, Wih_b, Whh_b, b_b);

    dim3 gg(1024 / BN, (B_ * S_) / BM);
    k_gemm_in<<<gg, 256>>>();

    k_lstm<<<32, 512>>>();

    k_outcrf<<<B_, 128>>>(y0, trans, Wout, bout, out);
}

// round 13
// speedup vs baseline: 1.3943x; 1.0331x over previous
#include <cuda_runtime.h>
#include <cuda_bf16.h>
#include <cstdint>

#define B_   128
#define S_   512
#define E_   300
#define KP   320     // padded K for GEMM
#define H_   128
#define G4   512     // 4*H
#define T_   12
#define SOS_ 3
#define EOS_ 4
#define NEGV (-10000.0f)

// ---------------- scratch (static device allocations) ----------------
__device__ __align__(16) __nv_bfloat16 g_emb[(size_t)B_*S_*KP];   // [65536][320]
__device__ __align__(16) __nv_bfloat16 g_wcat[1024*KP];           // [1024][320]
__device__ __align__(16) __nv_bfloat16 g_whh[2*G4*H_];            // [2][512][128]
__device__ float g_bias[1024];
__device__ float g_pre[(size_t)2*B_*S_*G4];                       // [2][128][512][512] fp32
__device__ __align__(16) __nv_bfloat16 g_hcat[(size_t)B_*S_*2*H_]; // [65536][256] bf16

// ---------------- helpers ----------------
__device__ __forceinline__ float tanhapx(float x) {
    float r; asm("tanh.approx.f32 %0, %1;" : "=f"(r) : "f"(x)); return r;
}
__device__ __forceinline__ float sigf(float x) {
    return 0.5f + 0.5f * tanhapx(0.5f * x);
}
__device__ __forceinline__ void cp16(void* smem, const void* gmem) {
    uint32_t s = (uint32_t)__cvta_generic_to_shared(smem);
    asm volatile("cp.async.cg.shared.global [%0], [%1], 16;\n" :: "r"(s), "l"(gmem) : "memory");
}
__device__ __forceinline__ void cp_commit() {
    asm volatile("cp.async.commit_group;\n" ::: "memory");
}
template<int N> __device__ __forceinline__ void cp_wait() {
    asm volatile("cp.async.wait_group %0;\n" :: "n"(N) : "memory");
}

// ---------------- K1: embedding gather -> bf16, K-padded (vectorized) ----------------
__global__ void k_prep_emb(const int* __restrict__ x, const float* __restrict__ embed) {
    const int row = blockIdx.x;          // 0..65535
    const int p   = threadIdx.x;         // 0..159 (pair index)
    const int xv  = x[row];
    __nv_bfloat162 v;
    if (p < E_ / 2) {
        float2 f = *(const float2*)&embed[(size_t)xv * E_ + p * 2];
        v = __floats2bfloat162_rn(f.x, f.y);
    } else {
        v = __floats2bfloat162_rn(0.0f, 0.0f);
    }
    *(__nv_bfloat162*)&g_emb[(size_t)row * KP + p * 2] = v;
}

// ---------------- K1b: weight packing ----------------
__global__ void k_prep_w(const float* __restrict__ Wih_f, const float* __restrict__ Whh_f,
                         const float* __restrict__ b_f,
                         const float* __restrict__ Wih_b, const float* __restrict__ Whh_b,
                         const float* __restrict__ b_b) {
    int idx = blockIdx.x * blockDim.x + threadIdx.x;
    const int NW = 1024 * KP;
    const int NH = 2 * G4 * H_;
    if (idx < NW) {
        int r = idx / KP, k = idx % KP;
        float v = 0.0f;
        if (k < E_) v = (r < G4) ? Wih_f[r * E_ + k] : Wih_b[(r - G4) * E_ + k];
        g_wcat[idx] = __float2bfloat16(v);
    } else if (idx < NW + NH) {
        int i = idx - NW;
        int d = i / (G4 * H_);
        int rem = i % (G4 * H_);
        float v = d ? Whh_b[rem] : Whh_f[rem];
        g_whh[i] = __float2bfloat16(v);
    } else if (idx < NW + NH + 1024) {
        int n = idx - NW - NH;
        g_bias[n] = (n < G4) ? b_f[n] : b_b[n - G4];
    }
}

// ---------------- K2: input GEMM, retiled BM=128 BN=128 (halve A L2 traffic) ----------------
// 256 threads = 8 warps (4m x 2n), warp tile 32x64: mi=2, ni=8, acc=64 regs.
// 2-stage cp.async pipeline (static smem cap).
#define BM 128
#define BN 128
#define BK 32
#define SA 40
#define KITERS (KP / BK)   // 10
#define NSTG 2

__global__ __launch_bounds__(256) void k_gemm_in() {
    __shared__ __align__(16) __nv_bfloat16 As[NSTG][BM * SA];
    __shared__ __align__(16) __nv_bfloat16 Bs[NSTG][BN * SA];
    const int m0 = blockIdx.y * BM;
    const int n0 = blockIdx.x * BN;
    const int tid = threadIdx.x;
    const int warp = tid >> 5, lane = tid & 31;
    const int wm = warp >> 1, wn = warp & 1;   // 4x2 warp grid, warp tile 32x64

    float acc[2][8][4];
    #pragma unroll
    for (int a = 0; a < 2; a++)
        #pragma unroll
        for (int b = 0; b < 8; b++)
            #pragma unroll
            for (int c = 0; c < 4; c++) acc[a][b][c] = 0.0f;

    const int lr = lane >> 2, lc = (lane & 3) * 2;
    const int ldr = tid >> 2, seg = tid & 3;
    const int lg = lane >> 3, lr8 = lane & 7;   // ldmatrix lane decomposition

    // ldmatrix base addresses (per stage)
    uint32_t aAddr[NSTG][2], bAddr[NSTG][2][2];
    #pragma unroll
    for (int st = 0; st < NSTG; st++) {
        #pragma unroll
        for (int mi = 0; mi < 2; mi++) {
            const int arow = wm * 32 + mi * 16 + lr8 + (lg & 1) * 8;
            const int acol = (lg >> 1) * 8;
            aAddr[st][mi] = (uint32_t)__cvta_generic_to_shared(
                &As[st][arow * SA + acol]);
        }
        #pragma unroll
        for (int ng = 0; ng < 2; ng++) {         // two 32-row n-groups
            const int brow = wn * 64 + ng * 32 + lg * 8 + lr8;
            #pragma unroll
            for (int kh = 0; kh < 2; kh++)
                bAddr[st][ng][kh] = (uint32_t)__cvta_generic_to_shared(
                    &Bs[st][brow * SA + kh * 8]);
        }
    }

    // prologue: stage 0 (A: 2 rows/thread, B: 2 rows/thread)
    cp16(&As[0][ldr * SA + seg * 8],        &g_emb[(size_t)(m0 + ldr) * KP + seg * 8]);
    cp16(&As[0][(ldr + 64) * SA + seg * 8], &g_emb[(size_t)(m0 + ldr + 64) * KP + seg * 8]);
    cp16(&Bs[0][ldr * SA + seg * 8],        &g_wcat[(size_t)(n0 + ldr) * KP + seg * 8]);
    cp16(&Bs[0][(ldr + 64) * SA + seg * 8], &g_wcat[(size_t)(n0 + ldr + 64) * KP + seg * 8]);
    cp_commit();

    for (int it = 0; it < KITERS; it++) {
        if (it + 1 < KITERS) {
            const int kt = (it + 1) * BK;
            const int st = (it + 1) & 1;
            cp16(&As[st][ldr * SA + seg * 8],        &g_emb[(size_t)(m0 + ldr) * KP + kt + seg * 8]);
            cp16(&As[st][(ldr + 64) * SA + seg * 8], &g_emb[(size_t)(m0 + ldr + 64) * KP + kt + seg * 8]);
            cp16(&Bs[st][ldr * SA + seg * 8],        &g_wcat[(size_t)(n0 + ldr) * KP + kt + seg * 8]);
            cp16(&Bs[st][(ldr + 64) * SA + seg * 8], &g_wcat[(size_t)(n0 + ldr + 64) * KP + kt + seg * 8]);
            cp_commit();
            cp_wait<1>();
        } else {
            cp_wait<0>();
        }
        __syncthreads();
        const int st = it & 1;
        #pragma unroll
        for (int ks = 0; ks < 2; ks++) {
            const uint32_t koff = (uint32_t)(ks * 16) * 2;   // bytes
            uint32_t a[2][4];
            #pragma unroll
            for (int mi = 0; mi < 2; mi++)
                asm volatile("ldmatrix.sync.aligned.m8n8.x4.shared.b16 {%0,%1,%2,%3}, [%4];\n"
                             : "=r"(a[mi][0]), "=r"(a[mi][1]), "=r"(a[mi][2]), "=r"(a[mi][3])
                             : "r"(aAddr[st][mi] + koff));
            uint32_t bfr[8][2];
            #pragma unroll
            for (int ng = 0; ng < 2; ng++)
                #pragma unroll
                for (int kh = 0; kh < 2; kh++)
                    asm volatile("ldmatrix.sync.aligned.m8n8.x4.shared.b16 {%0,%1,%2,%3}, [%4];\n"
                                 : "=r"(bfr[ng*4+0][kh]), "=r"(bfr[ng*4+1][kh]),
                                   "=r"(bfr[ng*4+2][kh]), "=r"(bfr[ng*4+3][kh])
                                 : "r"(bAddr[st][ng][kh] + koff));
            #pragma unroll
            for (int mi = 0; mi < 2; mi++)
                #pragma unroll
                for (int ni = 0; ni < 8; ni++) {
                    asm volatile(
                        "mma.sync.aligned.m16n8k16.row.col.f32.bf16.bf16.f32 "
                        "{%0,%1,%2,%3}, {%4,%5,%6,%7}, {%8,%9}, {%0,%1,%2,%3};\n"
                        : "+f"(acc[mi][ni][0]), "+f"(acc[mi][ni][1]),
                          "+f"(acc[mi][ni][2]), "+f"(acc[mi][ni][3])
                        : "r"(a[mi][0]), "r"(a[mi][1]), "r"(a[mi][2]), "r"(a[mi][3]),
                          "r"(bfr[ni][0]), "r"(bfr[ni][1]));
                }
        }
        __syncthreads();
    }
    // epilogue: add bias, scatter fp32 to PRE[d][b][s][j]
    #pragma unroll
    for (int mi = 0; mi < 2; mi++) {
        #pragma unroll
        for (int ni = 0; ni < 8; ni++) {
            int m = m0 + wm * 32 + mi * 16 + lr;
            int n = n0 + wn * 64 + ni * 8 + lc;
            int d = n >> 9, j = n & 511;
            float bias0 = g_bias[n], bias1 = g_bias[n + 1];
            {
                int bb = m >> 9, ss = m & 511;
                size_t base = (((size_t)(d * B_ + bb) * S_ + ss) * G4 + j);
                *(float2*)&g_pre[base] = make_float2(acc[mi][ni][0] + bias0,
                                                     acc[mi][ni][1] + bias1);
            }
            {
                int m2 = m + 8;
                int bb = m2 >> 9, ss = m2 & 511;
                size_t base = (((size_t)(d * B_ + bb) * S_ + ss) * G4 + j);
                *(float2*)&g_pre[base] = make_float2(acc[mi][ni][2] + bias0,
                                                     acc[mi][ni][3] + bias1);
            }
        }
    }
}

// ---------------- K3: tensor-core recurrence (proven config, unchanged) ----------------
#define HS 136   // h_sm row stride in bf16 (272B -> conflict-free ldmatrix)

__global__ __launch_bounds__(512, 1) void k_lstm() {
    __shared__ __align__(16) __nv_bfloat16 h_sm[2][16][HS];

    const int d   = blockIdx.x >> 4;
    const int bg  = blockIdx.x & 15;
    const int b0  = bg * 8;
    const int tid = threadIdx.x;
    const int w = tid >> 5, l = tid & 31;
    const int r = l >> 2, cpair = (l & 3) * 2;

    uint32_t Bf[4][8][2];
    #pragma unroll
    for (int ni = 0; ni < 4; ni++) {
        const int n = w * 8 + ni * 128 + r;
        const __nv_bfloat16* src = &g_whh[((size_t)d * G4 + n) * H_ + cpair];
        #pragma unroll
        for (int tk = 0; tk < 8; tk++) {
            Bf[ni][tk][0] = *(const uint32_t*)&src[tk * 16];
            Bf[ni][tk][1] = *(const uint32_t*)&src[tk * 16 + 8];
        }
    }
    for (int i = tid; i < 2 * 16 * HS; i += 512)
        ((__nv_bfloat16*)h_sm)[i] = __float2bfloat16(0.0f);

    const int b  = b0 + r;
    const int m0 = w * 8 + cpair;
    const int sgn = d ? -1 : 1;
    const int se0 = d ? (S_ - 1) : 0;

    const float* preb = &g_pre[((size_t)(d * B_ + b) * S_ + se0) * G4 + m0];
    __nv_bfloat16* hout = &g_hcat[((size_t)b * S_ + se0) * 256 + d * H_ + m0];
    const int preb_step = sgn * G4;
    const int hout_step = sgn * 256;

    float2 pf[4];
    #pragma unroll
    for (int ni = 0; ni < 4; ni++)
        pf[ni] = *(const float2*)&preb[ni * 128];

    float cA = 0.0f, cB = 0.0f;
    const uint32_t abase0 =
        (uint32_t)__cvta_generic_to_shared(&h_sm[0][l & 15][(l >> 4) * 8]);

    __syncthreads();

    int buf = 0;
    #pragma unroll 1
    for (int s = 0; s < S_; s++) {
        float acc[4][4];
        #pragma unroll
        for (int ni = 0; ni < 4; ni++) {
            acc[ni][0] = pf[ni].x; acc[ni][1] = pf[ni].y;
            acc[ni][2] = 0.0f;     acc[ni][3] = 0.0f;
        }
        if (s < S_ - 1) preb += preb_step;
        #pragma unroll
        for (int ni = 0; ni < 4; ni++)
            pf[ni] = *(const float2*)&preb[ni * 128];

        const uint32_t abase = abase0 + (uint32_t)buf * (16 * HS * 2);
        #pragma unroll
        for (int tk = 0; tk < 8; tk++) {
            uint32_t a0, a1, a2, a3;
            asm volatile("ldmatrix.sync.aligned.m8n8.x4.shared.b16 {%0,%1,%2,%3}, [%4];\n"
                         : "=r"(a0), "=r"(a1), "=r"(a2), "=r"(a3)
                         : "r"(abase + tk * 32));
            #pragma unroll
            for (int ni = 0; ni < 4; ni++) {
                asm volatile(
                    "mma.sync.aligned.m16n8k16.row.col.f32.bf16.bf16.f32 "
                    "{%0,%1,%2,%3}, {%4,%5,%6,%7}, {%8,%9}, {%0,%1,%2,%3};\n"
                    : "+f"(acc[ni][0]), "+f"(acc[ni][1]),
                      "+f"(acc[ni][2]), "+f"(acc[ni][3])
                    : "r"(a0), "r"(a1), "r"(a2), "r"(a3),
                      "r"(Bf[ni][tk][0]), "r"(Bf[ni][tk][1]));
            }
        }

        cA = sigf(acc[1][0]) * cA + sigf(acc[0][0]) * tanhapx(acc[2][0]);
        cB = sigf(acc[1][1]) * cB + sigf(acc[0][1]) * tanhapx(acc[2][1]);
        float hA = sigf(acc[3][0]) * tanhapx(cA);
        float hB = sigf(acc[3][1]) * tanhapx(cB);

        __nv_bfloat162 hpk = __floats2bfloat162_rn(hA, hB);
        *(__nv_bfloat162*)&h_sm[buf ^ 1][r][m0] = hpk;
        *(__nv_bfloat162*)hout = hpk;
        hout += hout_step;

        __syncthreads();
        buf ^= 1;
    }
}

// ---------------- K4: fused output linear + CRF forward + gold (unchanged) ----------------
__global__ __launch_bounds__(128) void k_outcrf(const int* __restrict__ y0,
                                                const float* __restrict__ trans,
                                                const float* __restrict__ Wout,
                                                const float* __restrict__ bout,
                                                float* __restrict__ out) {
    __shared__ float ysm[S_][T_];        // 24576 B
    __shared__ float wsm[T_][256];       // 12288 B
    __shared__ float tsm[T_][T_];
    __shared__ float esm[T_][T_];
    __shared__ float gpart[3];
    __shared__ float zsm;

    const int b = blockIdx.x;
    const int tid = threadIdx.x;
    const int lane = tid & 31, wrp = tid >> 5;

    for (int i = tid; i < T_ * 256; i += 128) wsm[0][i] = Wout[i];
    for (int i = tid; i < T_ * T_; i += 128) {
        float tv = trans[i];
        tsm[0][i] = tv;
        esm[0][i] = __expf(tv);    // exp(-1e4) = 0 exactly
    }
    if (tid < 3) gpart[tid] = 0.0f;
    __syncthreads();

    // ---- Phase 1: y = hcat @ Wout^T + bout ----
    const __nv_bfloat162* hbase = (const __nv_bfloat162*)&g_hcat[(size_t)b * S_ * 256];
    for (int idx = tid; idx < S_ * T_; idx += 128) {
        const int s = idx / T_, t = idx - s * T_;
        const __nv_bfloat162* hp = hbase + s * 128;
        const float2* wp = (const float2*)&wsm[t][0];
        float acc = bout[t];
        #pragma unroll 16
        for (int q = 0; q < 128; q++) {
            float2 h2 = __bfloat1622float2(hp[q]);
            float2 w2 = wp[q];
            acc += h2.x * w2.x + h2.y * w2.y;
        }
        ysm[s][t] = acc;
    }
    __syncthreads();

    // ---- Phase 2a: warps 1-3 compute gold path score ----
    if (wrp > 0) {
        const int* yb = &y0[b * S_];
        float g = 0.0f;
        for (int s = tid - 32; s < S_; s += 96) {
            int cur = yb[s];
            int prev = s ? yb[s - 1] : SOS_;
            g += ysm[s][cur] + tsm[cur][prev];
        }
        #pragma unroll
        for (int o = 16; o; o >>= 1) g += __shfl_xor_sync(0xffffffffu, g, o);
        if (lane == 0) gpart[wrp - 1] = g;
    }
    // ---- Phase 2b: warp 0 forward scan (exp-domain, lane-0 anchor) ----
    else {
        float e_row[T_];
        const int irow = (lane < T_) ? lane : 0;
        #pragma unroll
        for (int jj = 0; jj < T_; jj++) e_row[jj] = esm[irow][jj];

        float score = (lane < T_) ? tsm[irow][SOS_] + ysm[0][irow] : -1e30f;

        for (int s = 1; s < S_; s++) {
            float anchor = __shfl_sync(0xffffffffu, score, 0);
            float p = __expf(score - anchor);
            float Ssum = 0.0f;
            #pragma unroll
            for (int jj = 0; jj < T_; jj++)
                Ssum = fmaf(e_row[jj], __shfl_sync(0xffffffffu, p, jj), Ssum);
            float yv = ysm[s][irow];
            score = (lane < T_) ? anchor + __logf(Ssum) + yv : -1e30f;
        }
        float vz = (lane < T_) ? score + tsm[EOS_][irow] : -1e30f;
        float mz = vz;
        #pragma unroll
        for (int o = 16; o; o >>= 1) mz = fmaxf(mz, __shfl_xor_sync(0xffffffffu, mz, o));
        float ez = (lane < T_) ? __expf(vz - mz) : 0.0f;
        #pragma unroll
        for (int o = 16; o; o >>= 1) ez += __shfl_xor_sync(0xffffffffu, ez, o);
        if (lane == 0) zsm = mz + __logf(ez);
    }
    __syncthreads();
    if (tid == 0) {
        const int last = y0[b * S_ + S_ - 1];
        float gold = gpart[0] + gpart[1] + gpart[2] + tsm[EOS_][last];
        out[b] = zsm - gold;
    }
}

// ---------------- launcher ----------------
extern "C" void kernel_launch(void* const* d_in, const int* in_sizes, int n_in,
                              void* d_out, int out_size) {
    const int*   x     = (const int*)d_in[0];
    const int*   y0    = (const int*)d_in[1];
    const float* embed = (const float*)d_in[2];
    const float* Wih_f = (const float*)d_in[3];
    const float* Whh_f = (const float*)d_in[4];
    const float* b_f   = (const float*)d_in[5];
    const float* Wih_b = (const float*)d_in[6];
    const float* Whh_b = (const float*)d_in[7];
    const float* b_b   = (const float*)d_in[8];
    const float* Wout  = (const float*)d_in[9];
    const float* bout  = (const float*)d_in[10];
    const float* trans = (const float*)d_in[11];
    float* out = (float*)d_out;

    k_prep_emb<<<B_ * S_, KP / 2>>>(x, embed);

    const int prep_total = 1024 * KP + 2 * G4 * H_ + 1024;
    k_prep_w<<<(prep_total + 255) / 256, 256>>>(Wih_f, Whh_f, b_f, Wih_b, Whh_b, b_b);

    dim3 gg(1024 / BN, (B_ * S_) / BM);   // (8, 512)
    k_gemm_in<<<gg, 256>>>();

    k_lstm<<<32, 512>>>();

    k_outcrf<<<B_, 128>>>(y0, trans, Wout, bout, out);
}